// round 12
// baseline (speedup 1.0000x reference)
#include <cuda_runtime.h>
#include <cuda_bf16.h>
#include <math.h>
#include <stdint.h>

#define Nn 50000
#define Ee 1600000
#define Hh 128
#define NUc 49232
#define NMc 512
#define NSc 256
#define DEGCAP 128   // max degree capacity; E[deg]=32, sigma~5.7, P(deg>128)~1e-40

// ---------------- scratch (static device globals; no allocation) ----------------
__device__ float g_hm[(size_t)Nn * Hh];   // GEMM output (pre-aggregation), reused per layer
__device__ float g_ha[(size_t)Nn * Hh];   // ping (agg output)
__device__ float g_hb[(size_t)Nn * Hh];   // pong
__device__ float g_el[Nn];
__device__ float g_er[Nn];
__device__ int   g_cnt[Nn];
__device__ int   g_sfix[(size_t)Nn * DEGCAP];  // bucketed src lists (single-pass CSR)
__device__ float g_T[NMc * Hh];

// ---------------- single-pass bucketed CSR ----------------
__global__ void zero_cnt_kernel() {
    int i = blockIdx.x * blockDim.x + threadIdx.x;
    if (i < Nn) g_cnt[i] = 0;
}

__global__ void scatter1_kernel(const int* __restrict__ src, const int* __restrict__ dst) {
    int stride = gridDim.x * blockDim.x;
    const int4* s4p = (const int4*)src;
    const int4* d4p = (const int4*)dst;
    for (int i = blockIdx.x * blockDim.x + threadIdx.x; i < Ee / 4; i += stride) {
        int4 d4 = d4p[i];
        int4 s4 = s4p[i];
        int p;
        p = atomicAdd(&g_cnt[d4.x], 1); if (p < DEGCAP) g_sfix[(size_t)d4.x * DEGCAP + p] = s4.x;
        p = atomicAdd(&g_cnt[d4.y], 1); if (p < DEGCAP) g_sfix[(size_t)d4.y * DEGCAP + p] = s4.y;
        p = atomicAdd(&g_cnt[d4.z], 1); if (p < DEGCAP) g_sfix[(size_t)d4.z * DEGCAP + p] = s4.z;
        p = atomicAdd(&g_cnt[d4.w], 1); if (p < DEGCAP) g_sfix[(size_t)d4.w * DEGCAP + p] = s4.w;
    }
}

// ---------------- bf16 tensor-core GEMM, 2-term split, packed uint4 B fragments ----------------
__device__ __forceinline__ void mma_bf16(float c[4], uint32_t a0, uint32_t a1, uint32_t a2, uint32_t a3,
                                         uint32_t b0, uint32_t b1) {
    asm volatile(
        "mma.sync.aligned.m16n8k16.row.col.f32.bf16.bf16.f32 "
        "{%0,%1,%2,%3}, {%4,%5,%6,%7}, {%8,%9}, {%0,%1,%2,%3};"
        : "+f"(c[0]), "+f"(c[1]), "+f"(c[2]), "+f"(c[3])
        : "r"(a0), "r"(a1), "r"(a2), "r"(a3), "r"(b0), "r"(b1));
}

__device__ __forceinline__ void split_bf16x2(float x0, float x1, uint32_t& hi, uint32_t& lo) {
    __nv_bfloat162 h = __floats2bfloat162_rn(x0, x1);
    float2 hf = __bfloat1622float2(h);
    __nv_bfloat162 l = __floats2bfloat162_rn(x0 - hf.x, x1 - hf.y);
    hi = *(uint32_t*)&h;
    lo = *(uint32_t*)&l;
}

#define NSTRIDE 36   // uint4s per n row (32 data + 4 pad -> bank shift of 16 per n)

__global__ __launch_bounds__(256, 2)
void gemm_bf16_kernel(const float* __restrict__ X, const float* __restrict__ W,
                      const float* __restrict__ al, const float* __restrict__ ar,
                      float* __restrict__ Hout, int nrows, int compute_elr) {
    extern __shared__ uint4 Wp[];   // [128][NSTRIDE]

    // stage W: compile-time 16 iterations -> full MLP on the 64 LDGs
    {
        int t = threadIdx.x;
#pragma unroll
        for (int it = 0; it < 16; ++it) {
            int i = it * 256 + t;
            int n = i & 127;
            int r = i >> 7;              // 0..31
            int kt = r >> 2, tig = r & 3;
            int k0 = kt * 16 + 2 * tig;
            float w00 = W[(size_t)k0 * Hh + n];
            float w01 = W[(size_t)(k0 + 1) * Hh + n];
            float w10 = W[(size_t)(k0 + 8) * Hh + n];
            float w11 = W[(size_t)(k0 + 9) * Hh + n];
            uint4 v;
            split_bf16x2(w00, w01, v.x, v.z);
            split_bf16x2(w10, w11, v.y, v.w);
            Wp[n * NSTRIDE + kt * 4 + tig] = v;
        }
    }
    __syncthreads();

    const unsigned FULL = 0xffffffffu;
    int lane = threadIdx.x & 31;
    int warp = threadIdx.x >> 5;
    int g = lane >> 2, tig = lane & 3;
    int gw = blockIdx.x * (blockDim.x >> 5) + warp;
    int nwarps = gridDim.x * (blockDim.x >> 5);
    int ngroups = (nrows + 15) >> 4;

    for (int grp = gw; grp < ngroups; grp += nwarps) {
        int row0 = grp * 16;
        int rA = row0 + g, rB = row0 + g + 8;
        bool vA = rA < nrows, vB = rB < nrows;

        float c[16][4];
#pragma unroll
        for (int nt = 0; nt < 16; ++nt) {
            c[nt][0] = 0.f; c[nt][1] = 0.f; c[nt][2] = 0.f; c[nt][3] = 0.f;
        }

#pragma unroll 2
        for (int kt = 0; kt < 8; ++kt) {
            int k0 = kt * 16;
            float2 z2 = make_float2(0.f, 0.f);
            float2 xa0 = vA ? *(const float2*)(X + (size_t)rA * Hh + k0 + 2 * tig)     : z2;
            float2 xa1 = vA ? *(const float2*)(X + (size_t)rA * Hh + k0 + 2 * tig + 8) : z2;
            float2 xb0 = vB ? *(const float2*)(X + (size_t)rB * Hh + k0 + 2 * tig)     : z2;
            float2 xb1 = vB ? *(const float2*)(X + (size_t)rB * Hh + k0 + 2 * tig + 8) : z2;

            uint32_t ahi[4], alo[4];
            split_bf16x2(xa0.x, xa0.y, ahi[0], alo[0]);
            split_bf16x2(xb0.x, xb0.y, ahi[1], alo[1]);
            split_bf16x2(xa1.x, xa1.y, ahi[2], alo[2]);
            split_bf16x2(xb1.x, xb1.y, ahi[3], alo[3]);

            const uint4* wrow = Wp + (size_t)kt * 4 + tig;
#pragma unroll
            for (int nt = 0; nt < 16; ++nt) {
                int n = nt * 8 + g;
                uint4 b = wrow[n * NSTRIDE];
                mma_bf16(c[nt], ahi[0], ahi[1], ahi[2], ahi[3], b.x, b.y);  // hi*hi
                mma_bf16(c[nt], ahi[0], ahi[1], ahi[2], ahi[3], b.z, b.w);  // hi*lo
                mma_bf16(c[nt], alo[0], alo[1], alo[2], alo[3], b.x, b.y);  // lo*hi
            }
        }

        float pal = 0.f, par = 0.f, pbl = 0.f, pbr = 0.f;
#pragma unroll
        for (int nt = 0; nt < 16; ++nt) {
            int col = nt * 8 + 2 * tig;
            if (vA) *(float2*)&Hout[(size_t)rA * Hh + col] = make_float2(c[nt][0], c[nt][1]);
            if (vB) *(float2*)&Hout[(size_t)rB * Hh + col] = make_float2(c[nt][2], c[nt][3]);
            if (compute_elr) {
                float a0 = al[col], a1 = al[col + 1];
                float r0v = ar[col], r1v = ar[col + 1];
                pal += c[nt][0] * a0 + c[nt][1] * a1;
                par += c[nt][0] * r0v + c[nt][1] * r1v;
                pbl += c[nt][2] * a0 + c[nt][3] * a1;
                pbr += c[nt][2] * r0v + c[nt][3] * r1v;
            }
        }
        if (compute_elr) {
#pragma unroll
            for (int o = 1; o < 4; o <<= 1) {
                pal += __shfl_xor_sync(FULL, pal, o);
                par += __shfl_xor_sync(FULL, par, o);
                pbl += __shfl_xor_sync(FULL, pbl, o);
                pbr += __shfl_xor_sync(FULL, pbr, o);
            }
            if (tig == 0) {
                if (vA) { g_el[rA] = pal; g_er[rA] = par; }
                if (vB) { g_el[rB] = pbl; g_er[rB] = pbr; }
            }
        }
    }
}

// ---------------- fused edge softmax + aggregation (2 nodes per warp, interleaved chains) ----------------
__global__ void agg_kernel(const float* __restrict__ h, const float* __restrict__ bias,
                           float* __restrict__ hout, int do_relu) {
    int lane = threadIdx.x & 31;
    int w = (blockIdx.x * blockDim.x + threadIdx.x) >> 5;
    int v0 = w * 2;              // Nn even; grid sized so v0+1 < Nn
    int v1 = v0 + 1;
    if (v0 >= Nn) return;

    int deg0 = min(g_cnt[v0], DEGCAP);
    int deg1 = min(g_cnt[v1], DEGCAP);
    const int* row0 = g_sfix + (size_t)v0 * DEGCAP;
    const int* row1 = g_sfix + (size_t)v1 * DEGCAP;
    float el0 = g_el[v0];
    float el1 = g_el[v1];

    float4 a0 = make_float4(0.f, 0.f, 0.f, 0.f);
    float4 a1 = make_float4(0.f, 0.f, 0.f, 0.f);
    float s0 = 0.f, s1 = 0.f;
    int dm = max(deg0, deg1);
#pragma unroll 2
    for (int i = 0; i < dm; ++i) {
        // two independent load chains per iteration -> 2x MLP
        if (i < deg0) {
            int sv = row0[i];
            float e = el0 + g_er[sv];
            e = e > 0.f ? e : 0.2f * e;
            float wt = __expf(e);
            s0 += wt;
            float4 hv = *(const float4*)(h + (size_t)sv * Hh + lane * 4);
            a0.x += wt * hv.x; a0.y += wt * hv.y; a0.z += wt * hv.z; a0.w += wt * hv.w;
        }
        if (i < deg1) {
            int sv = row1[i];
            float e = el1 + g_er[sv];
            e = e > 0.f ? e : 0.2f * e;
            float wt = __expf(e);
            s1 += wt;
            float4 hv = *(const float4*)(h + (size_t)sv * Hh + lane * 4);
            a1.x += wt * hv.x; a1.y += wt * hv.y; a1.z += wt * hv.z; a1.w += wt * hv.w;
        }
    }

    float4 bv = *(const float4*)(bias + lane * 4);
    float inv0 = 1.f / (s0 + 1e-10f);
    float inv1 = 1.f / (s1 + 1e-10f);
    float4 o0, o1;
    o0.x = a0.x * inv0 + bv.x; o0.y = a0.y * inv0 + bv.y;
    o0.z = a0.z * inv0 + bv.z; o0.w = a0.w * inv0 + bv.w;
    o1.x = a1.x * inv1 + bv.x; o1.y = a1.y * inv1 + bv.y;
    o1.z = a1.z * inv1 + bv.z; o1.w = a1.w * inv1 + bv.w;
    if (do_relu) {
        o0.x = fmaxf(o0.x, 0.f); o0.y = fmaxf(o0.y, 0.f);
        o0.z = fmaxf(o0.z, 0.f); o0.w = fmaxf(o0.w, 0.f);
        o1.x = fmaxf(o1.x, 0.f); o1.y = fmaxf(o1.y, 0.f);
        o1.z = fmaxf(o1.z, 0.f); o1.w = fmaxf(o1.w, 0.f);
    }
    *(float4*)(hout + (size_t)v0 * Hh + lane * 4) = o0;
    *(float4*)(hout + (size_t)v1 * Hh + lane * 4) = o1;
}

// ---------------- scores = T @ server^T + bb ----------------
__global__ void scores_kernel(const float* __restrict__ Tm, const float* __restrict__ S,
                              const float* __restrict__ bb, float* __restrict__ out) {
    const unsigned FULL = 0xffffffffu;
    int lane = threadIdx.x & 31;
    int w = (blockIdx.x * blockDim.x + threadIdx.x) >> 5;
    if (w >= NMc * 8) return;
    int m = w >> 3;
    int sbase = (w & 7) * 32;
    float4 t = ((const float4*)(Tm + (size_t)m * Hh))[lane];
    float b = bb[0];
    for (int j = 0; j < 32; ++j) {
        int sidx = sbase + j;
        float4 sv = ((const float4*)(S + (size_t)sidx * Hh))[lane];
        float d = t.x * sv.x + t.y * sv.y + t.z * sv.z + t.w * sv.w;
#pragma unroll
        for (int o = 16; o; o >>= 1) d += __shfl_xor_sync(FULL, d, o);
        if (lane == 0) out[m * NSc + sidx] = d + b;
    }
}

// ---------------- launch ----------------
extern "C" void kernel_launch(void* const* d_in, const int* in_sizes, int n_in,
                              void* d_out, int out_size) {
    (void)in_sizes; (void)n_in; (void)out_size;
    const float* x   = (const float*)d_in[0];
    const int*   ei  = (const int*)d_in[1];
    const float* W1  = (const float*)d_in[2];
    const float* al1 = (const float*)d_in[3];
    const float* ar1 = (const float*)d_in[4];
    const float* b1  = (const float*)d_in[5];
    const float* W2  = (const float*)d_in[6];
    const float* al2 = (const float*)d_in[7];
    const float* ar2 = (const float*)d_in[8];
    const float* b2  = (const float*)d_in[9];
    const float* W3  = (const float*)d_in[10];
    const float* al3 = (const float*)d_in[11];
    const float* ar3 = (const float*)d_in[12];
    const float* b3  = (const float*)d_in[13];
    const float* Wb  = (const float*)d_in[14];
    const float* bb  = (const float*)d_in[15];
    float* out = (float*)d_out;

    const int* src = ei;
    const int* dst = ei + Ee;

    // one-time resources (created on the first, non-captured, correctness call)
    static cudaStream_t s2 = nullptr;
    static cudaEvent_t evFork = nullptr, evJoin = nullptr;
    if (s2 == nullptr) {
        cudaStreamCreateWithFlags(&s2, cudaStreamNonBlocking);
        cudaEventCreateWithFlags(&evFork, cudaEventDisableTiming);
        cudaEventCreateWithFlags(&evJoin, cudaEventDisableTiming);
    }

    const int SMEM_GEMM = 128 * NSTRIDE * 16;   // 73728 B -> 2 CTAs/SM
    cudaFuncSetAttribute(gemm_bf16_kernel, cudaFuncAttributeMaxDynamicSharedMemorySize, SMEM_GEMM);

    float *hm, *ha, *hb, *Tp;
    cudaGetSymbolAddress((void**)&hm, g_hm);
    cudaGetSymbolAddress((void**)&ha, g_ha);
    cudaGetSymbolAddress((void**)&hb, g_hb);
    cudaGetSymbolAddress((void**)&Tp, g_T);

    const int GEMM_GRID = 391;
    const int AGG_GRID  = (Nn / 2 * 32 + 255) / 256;   // 2 nodes per warp -> 3125 blocks

    // fork: CSR build (zero + single-pass bucket scatter) on s2, gemm1 on main
    cudaEventRecord(evFork, 0);
    cudaStreamWaitEvent(s2, evFork, 0);
    zero_cnt_kernel<<<(Nn + 255) / 256, 256, 0, s2>>>();                          // 1
    scatter1_kernel<<<2048, 256, 0, s2>>>(src, dst);                              // 2
    cudaEventRecord(evJoin, s2);

    gemm_bf16_kernel<<<GEMM_GRID, 256, SMEM_GEMM>>>(x, W1, al1, ar1, hm, Nn, 1);  // 3

    // join: agg1 needs both gemm1 and CSR
    cudaStreamWaitEvent(0, evJoin, 0);
    agg_kernel<<<AGG_GRID, 256>>>(hm, b1, ha, 1);                                 // 4 (profiled slot)
    // layer 2
    gemm_bf16_kernel<<<GEMM_GRID, 256, SMEM_GEMM>>>(ha, W2, al2, ar2, hm, Nn, 1);
    agg_kernel<<<AGG_GRID, 256>>>(hm, b2, hb, 1);
    // layer 3
    gemm_bf16_kernel<<<GEMM_GRID, 256, SMEM_GEMM>>>(hb, W3, al3, ar3, hm, Nn, 1);
    agg_kernel<<<AGG_GRID, 256>>>(hm, b3, ha, 0);

    // bilinear head
    gemm_bf16_kernel<<<4, 256, SMEM_GEMM>>>(ha + (size_t)NUc * Hh, Wb, al1, ar1, Tp, NMc, 0);
    scores_kernel<<<512, 256>>>(Tp, ha + (size_t)(NUc + NMc) * Hh, bb, out);
}

// round 13
// speedup vs baseline: 1.3568x; 1.3568x over previous
#include <cuda_runtime.h>
#include <cuda_bf16.h>
#include <math.h>
#include <stdint.h>

#define Nn 50000
#define Ee 1600000
#define Hh 128
#define NUc 49232
#define NMc 512
#define NSc 256
#define DEGCAP 128   // max degree capacity; E[deg]=32, sigma~5.7, P(deg>128)~1e-40

// ---------------- scratch (static device globals; no allocation) ----------------
__device__ float g_hm[(size_t)Nn * Hh];   // GEMM output (pre-aggregation), reused per layer
__device__ float g_ha[(size_t)Nn * Hh];   // ping (agg output)
__device__ float g_hb[(size_t)Nn * Hh];   // pong
__device__ float g_el[Nn];
__device__ float g_er[Nn];
__device__ int   g_cnt[Nn];
__device__ int   g_sfix[(size_t)Nn * DEGCAP];  // bucketed src lists (single-pass CSR)
__device__ float g_T[NMc * Hh];

// ---------------- single-pass bucketed CSR ----------------
__global__ void zero_cnt_kernel() {
    int i = blockIdx.x * blockDim.x + threadIdx.x;
    if (i < Nn) g_cnt[i] = 0;
}

__global__ void scatter1_kernel(const int* __restrict__ src, const int* __restrict__ dst) {
    int stride = gridDim.x * blockDim.x;
    const int4* s4p = (const int4*)src;
    const int4* d4p = (const int4*)dst;
    for (int i = blockIdx.x * blockDim.x + threadIdx.x; i < Ee / 4; i += stride) {
        int4 d4 = d4p[i];
        int4 s4 = s4p[i];
        int p;
        p = atomicAdd(&g_cnt[d4.x], 1); if (p < DEGCAP) g_sfix[(size_t)d4.x * DEGCAP + p] = s4.x;
        p = atomicAdd(&g_cnt[d4.y], 1); if (p < DEGCAP) g_sfix[(size_t)d4.y * DEGCAP + p] = s4.y;
        p = atomicAdd(&g_cnt[d4.z], 1); if (p < DEGCAP) g_sfix[(size_t)d4.z * DEGCAP + p] = s4.z;
        p = atomicAdd(&g_cnt[d4.w], 1); if (p < DEGCAP) g_sfix[(size_t)d4.w * DEGCAP + p] = s4.w;
    }
}

// ---------------- bf16 tensor-core GEMM, 2-term split, packed uint4 B fragments ----------------
__device__ __forceinline__ void mma_bf16(float c[4], uint32_t a0, uint32_t a1, uint32_t a2, uint32_t a3,
                                         uint32_t b0, uint32_t b1) {
    asm volatile(
        "mma.sync.aligned.m16n8k16.row.col.f32.bf16.bf16.f32 "
        "{%0,%1,%2,%3}, {%4,%5,%6,%7}, {%8,%9}, {%0,%1,%2,%3};"
        : "+f"(c[0]), "+f"(c[1]), "+f"(c[2]), "+f"(c[3])
        : "r"(a0), "r"(a1), "r"(a2), "r"(a3), "r"(b0), "r"(b1));
}

__device__ __forceinline__ void split_bf16x2(float x0, float x1, uint32_t& hi, uint32_t& lo) {
    __nv_bfloat162 h = __floats2bfloat162_rn(x0, x1);
    float2 hf = __bfloat1622float2(h);
    __nv_bfloat162 l = __floats2bfloat162_rn(x0 - hf.x, x1 - hf.y);
    hi = *(uint32_t*)&h;
    lo = *(uint32_t*)&l;
}

#define NSTRIDE 36   // uint4s per n row (32 data + 4 pad -> bank shift of 16 per n)

__global__ __launch_bounds__(256, 2)
void gemm_bf16_kernel(const float* __restrict__ X, const float* __restrict__ W,
                      const float* __restrict__ al, const float* __restrict__ ar,
                      float* __restrict__ Hout, int nrows, int compute_elr) {
    extern __shared__ uint4 Wp[];   // [128][NSTRIDE]

    // stage W: compile-time 16 iterations -> full MLP on the 64 LDGs
    {
        int t = threadIdx.x;
#pragma unroll
        for (int it = 0; it < 16; ++it) {
            int i = it * 256 + t;
            int n = i & 127;
            int r = i >> 7;              // 0..31
            int kt = r >> 2, tig = r & 3;
            int k0 = kt * 16 + 2 * tig;
            float w00 = W[(size_t)k0 * Hh + n];
            float w01 = W[(size_t)(k0 + 1) * Hh + n];
            float w10 = W[(size_t)(k0 + 8) * Hh + n];
            float w11 = W[(size_t)(k0 + 9) * Hh + n];
            uint4 v;
            split_bf16x2(w00, w01, v.x, v.z);
            split_bf16x2(w10, w11, v.y, v.w);
            Wp[n * NSTRIDE + kt * 4 + tig] = v;
        }
    }
    __syncthreads();

    const unsigned FULL = 0xffffffffu;
    int lane = threadIdx.x & 31;
    int warp = threadIdx.x >> 5;
    int g = lane >> 2, tig = lane & 3;
    int gw = blockIdx.x * (blockDim.x >> 5) + warp;
    int nwarps = gridDim.x * (blockDim.x >> 5);
    int ngroups = (nrows + 15) >> 4;

    for (int grp = gw; grp < ngroups; grp += nwarps) {
        int row0 = grp * 16;
        int rA = row0 + g, rB = row0 + g + 8;
        bool vA = rA < nrows, vB = rB < nrows;

        float c[16][4];
#pragma unroll
        for (int nt = 0; nt < 16; ++nt) {
            c[nt][0] = 0.f; c[nt][1] = 0.f; c[nt][2] = 0.f; c[nt][3] = 0.f;
        }

#pragma unroll 2
        for (int kt = 0; kt < 8; ++kt) {
            int k0 = kt * 16;
            float2 z2 = make_float2(0.f, 0.f);
            float2 xa0 = vA ? *(const float2*)(X + (size_t)rA * Hh + k0 + 2 * tig)     : z2;
            float2 xa1 = vA ? *(const float2*)(X + (size_t)rA * Hh + k0 + 2 * tig + 8) : z2;
            float2 xb0 = vB ? *(const float2*)(X + (size_t)rB * Hh + k0 + 2 * tig)     : z2;
            float2 xb1 = vB ? *(const float2*)(X + (size_t)rB * Hh + k0 + 2 * tig + 8) : z2;

            uint32_t ahi[4], alo[4];
            split_bf16x2(xa0.x, xa0.y, ahi[0], alo[0]);
            split_bf16x2(xb0.x, xb0.y, ahi[1], alo[1]);
            split_bf16x2(xa1.x, xa1.y, ahi[2], alo[2]);
            split_bf16x2(xb1.x, xb1.y, ahi[3], alo[3]);

            const uint4* wrow = Wp + (size_t)kt * 4 + tig;
#pragma unroll
            for (int nt = 0; nt < 16; ++nt) {
                int n = nt * 8 + g;
                uint4 b = wrow[n * NSTRIDE];
                mma_bf16(c[nt], ahi[0], ahi[1], ahi[2], ahi[3], b.x, b.y);  // hi*hi
                mma_bf16(c[nt], ahi[0], ahi[1], ahi[2], ahi[3], b.z, b.w);  // hi*lo
                mma_bf16(c[nt], alo[0], alo[1], alo[2], alo[3], b.x, b.y);  // lo*hi
            }
        }

        float pal = 0.f, par = 0.f, pbl = 0.f, pbr = 0.f;
#pragma unroll
        for (int nt = 0; nt < 16; ++nt) {
            int col = nt * 8 + 2 * tig;
            if (vA) *(float2*)&Hout[(size_t)rA * Hh + col] = make_float2(c[nt][0], c[nt][1]);
            if (vB) *(float2*)&Hout[(size_t)rB * Hh + col] = make_float2(c[nt][2], c[nt][3]);
            if (compute_elr) {
                float a0 = al[col], a1 = al[col + 1];
                float r0v = ar[col], r1v = ar[col + 1];
                pal += c[nt][0] * a0 + c[nt][1] * a1;
                par += c[nt][0] * r0v + c[nt][1] * r1v;
                pbl += c[nt][2] * a0 + c[nt][3] * a1;
                pbr += c[nt][2] * r0v + c[nt][3] * r1v;
            }
        }
        if (compute_elr) {
#pragma unroll
            for (int o = 1; o < 4; o <<= 1) {
                pal += __shfl_xor_sync(FULL, pal, o);
                par += __shfl_xor_sync(FULL, par, o);
                pbl += __shfl_xor_sync(FULL, pbl, o);
                pbr += __shfl_xor_sync(FULL, pbr, o);
            }
            if (tig == 0) {
                if (vA) { g_el[rA] = pal; g_er[rA] = par; }
                if (vB) { g_el[rB] = pbl; g_er[rB] = pbr; }
            }
        }
    }
}

// ---------------- fused edge softmax + aggregation (warp per node; node range) ----------------
__global__ void agg_kernel(const float* __restrict__ h, const float* __restrict__ bias,
                           float* __restrict__ hout, int do_relu, int vbase, int vcount) {
    int lane = threadIdx.x & 31;
    int idx = (blockIdx.x * blockDim.x + threadIdx.x) >> 5;
    if (idx >= vcount) return;
    int v = vbase + idx;

    int deg = min(g_cnt[v], DEGCAP);
    const int* srow = g_sfix + (size_t)v * DEGCAP;
    float elv = g_el[v];

    float4 acc = make_float4(0.f, 0.f, 0.f, 0.f);
    float s = 0.f;
#pragma unroll 4
    for (int i = 0; i < deg; ++i) {
        int sv = srow[i];
        float e = elv + g_er[sv];
        e = e > 0.f ? e : 0.2f * e;
        float w = __expf(e);
        s += w;
        float4 hv = *(const float4*)(h + (size_t)sv * Hh + lane * 4);
        acc.x += w * hv.x;
        acc.y += w * hv.y;
        acc.z += w * hv.z;
        acc.w += w * hv.w;
    }

    float inv = 1.f / (s + 1e-10f);
    float4 bv = *(const float4*)(bias + lane * 4);
    float4 o;
    o.x = acc.x * inv + bv.x;
    o.y = acc.y * inv + bv.y;
    o.z = acc.z * inv + bv.z;
    o.w = acc.w * inv + bv.w;
    if (do_relu) {
        o.x = fmaxf(o.x, 0.f);
        o.y = fmaxf(o.y, 0.f);
        o.z = fmaxf(o.z, 0.f);
        o.w = fmaxf(o.w, 0.f);
    }
    *(float4*)(hout + (size_t)v * Hh + lane * 4) = o;
}

// ---------------- scores = T @ server^T + bb ----------------
__global__ void scores_kernel(const float* __restrict__ Tm, const float* __restrict__ S,
                              const float* __restrict__ bb, float* __restrict__ out) {
    const unsigned FULL = 0xffffffffu;
    int lane = threadIdx.x & 31;
    int w = (blockIdx.x * blockDim.x + threadIdx.x) >> 5;
    if (w >= NMc * 8) return;
    int m = w >> 3;
    int sbase = (w & 7) * 32;
    float4 t = ((const float4*)(Tm + (size_t)m * Hh))[lane];
    float b = bb[0];
    for (int j = 0; j < 32; ++j) {
        int sidx = sbase + j;
        float4 sv = ((const float4*)(S + (size_t)sidx * Hh))[lane];
        float d = t.x * sv.x + t.y * sv.y + t.z * sv.z + t.w * sv.w;
#pragma unroll
        for (int o = 16; o; o >>= 1) d += __shfl_xor_sync(FULL, d, o);
        if (lane == 0) out[m * NSc + sidx] = d + b;
    }
}

// ---------------- launch ----------------
extern "C" void kernel_launch(void* const* d_in, const int* in_sizes, int n_in,
                              void* d_out, int out_size) {
    (void)in_sizes; (void)n_in; (void)out_size;
    const float* x   = (const float*)d_in[0];
    const int*   ei  = (const int*)d_in[1];
    const float* W1  = (const float*)d_in[2];
    const float* al1 = (const float*)d_in[3];
    const float* ar1 = (const float*)d_in[4];
    const float* b1  = (const float*)d_in[5];
    const float* W2  = (const float*)d_in[6];
    const float* al2 = (const float*)d_in[7];
    const float* ar2 = (const float*)d_in[8];
    const float* b2  = (const float*)d_in[9];
    const float* W3  = (const float*)d_in[10];
    const float* al3 = (const float*)d_in[11];
    const float* ar3 = (const float*)d_in[12];
    const float* b3  = (const float*)d_in[13];
    const float* Wb  = (const float*)d_in[14];
    const float* bb  = (const float*)d_in[15];
    float* out = (float*)d_out;

    const int* src = ei;
    const int* dst = ei + Ee;

    // one-time resources (created on the first, non-captured, correctness call)
    static cudaStream_t s2 = nullptr;
    static cudaEvent_t evFork = nullptr, evJoin = nullptr;
    if (s2 == nullptr) {
        cudaStreamCreateWithFlags(&s2, cudaStreamNonBlocking);
        cudaEventCreateWithFlags(&evFork, cudaEventDisableTiming);
        cudaEventCreateWithFlags(&evJoin, cudaEventDisableTiming);
    }

    const int SMEM_GEMM = 128 * NSTRIDE * 16;   // 73728 B -> 2 CTAs/SM
    cudaFuncSetAttribute(gemm_bf16_kernel, cudaFuncAttributeMaxDynamicSharedMemorySize, SMEM_GEMM);

    float *hm, *ha, *hb, *Tp;
    cudaGetSymbolAddress((void**)&hm, g_hm);
    cudaGetSymbolAddress((void**)&ha, g_ha);
    cudaGetSymbolAddress((void**)&hb, g_hb);
    cudaGetSymbolAddress((void**)&Tp, g_T);

    const int GEMM_GRID = 391;
    const int AGG_GRID_FULL = (Nn * 32 + 255) / 256;        // warp per node, all nodes
    const int NOUT = NMc + NSc;                             // 768 nodes consumed from layer 3
    const int AGG_GRID_OUT  = (NOUT * 32 + 255) / 256;      // 96 blocks

    // fork: CSR build (zero + single-pass bucket scatter) on s2, gemm1 on main
    cudaEventRecord(evFork, 0);
    cudaStreamWaitEvent(s2, evFork, 0);
    zero_cnt_kernel<<<(Nn + 255) / 256, 256, 0, s2>>>();                          // 1
    scatter1_kernel<<<2048, 256, 0, s2>>>(src, dst);                              // 2
    cudaEventRecord(evJoin, s2);

    gemm_bf16_kernel<<<GEMM_GRID, 256, SMEM_GEMM>>>(x, W1, al1, ar1, hm, Nn, 1);  // 3

    // join: agg1 needs both gemm1 and CSR
    cudaStreamWaitEvent(0, evJoin, 0);
    agg_kernel<<<AGG_GRID_FULL, 256>>>(hm, b1, ha, 1, 0, Nn);                     // 4 (profiled slot)
    // layer 2
    gemm_bf16_kernel<<<GEMM_GRID, 256, SMEM_GEMM>>>(ha, W2, al2, ar2, hm, Nn, 1);
    agg_kernel<<<AGG_GRID_FULL, 256>>>(hm, b2, hb, 1, 0, Nn);
    // layer 3: GEMM over all nodes (sources), aggregation ONLY over the 768 consumed nodes
    gemm_bf16_kernel<<<GEMM_GRID, 256, SMEM_GEMM>>>(hb, W3, al3, ar3, hm, Nn, 1);
    agg_kernel<<<AGG_GRID_OUT, 256>>>(hm, b3, ha, 0, NUc, NOUT);

    // bilinear head
    gemm_bf16_kernel<<<4, 256, SMEM_GEMM>>>(ha + (size_t)NUc * Hh, Wb, al1, ar1, Tp, NMc, 0);
    scores_kernel<<<512, 256>>>(Tp, ha + (size_t)(NUc + NMc) * Hh, bb, out);
}